// round 3
// baseline (speedup 1.0000x reference)
#include <cuda_runtime.h>

// LinearMimo: batched MIMO IIR filter.
// B=32, T=16384, I=8, O=8, NB=3 (FIR taps), NA=2 (IIR order).
// y[b,t,o] = sum_i x_{b,o,i}[t]
// x[t] = b0*u[t] + b1*u[t-1] + b2*u[t-2] - a0*x[t-1] - a1*x[t-2]
//
// Strategy: chunked-parallel with warm-up. Poles are well inside the unit
// circle (|lambda| <~ 0.5), so a 64-step warm-up with zero state converges to
// the true trajectory to ~1e-19 relative. T split into 32 chunks of 512.
// Thread handles 2 input channels (i-pair) for one (b, o, chunk):
//   32 b * 8 o * 4 pairs * 32 chunks = 32768 threads = 1024 warps.
// Warp layout: lane = j + 4*o  (j = i-pair 0..3, o = 0..7), fixed (b, chunk).
//   - u load: float2 per lane, warp hits one 32B sector per t.
//   - reduction over i: local add + 2x shfl.bfly within 4-lane groups.
//   - store: 8 writer lanes (j==0) -> y[b,t,0..7], 32B contiguous.

#define NB_B 32
#define NT_T 16384
#define NI_I 8
#define NO_O 8
#define NCHUNK 32
#define CHUNK_L 512
#define WARMUP 64

__global__ __launch_bounds__(256, 8)
void linear_mimo_kernel(const float* __restrict__ b_coeff,   // (O, I, 3)
                        const float* __restrict__ a_coeff,   // (O, I, 2)
                        const float* __restrict__ u_in,      // (B, T, I)
                        const float* __restrict__ y_0,       // (B, O, I, 2)
                        const float* __restrict__ u_0,       // (B, I, 3)
                        float* __restrict__ y_out)           // (B, T, O)
{
    const int tid  = blockIdx.x * blockDim.x + threadIdx.x;
    const int lane = threadIdx.x & 31;
    const int w    = tid >> 5;            // global warp id 0..1023
    const int b    = w & (NB_B - 1);      // batch
    const int c    = w >> 5;              // chunk 0..31
    const int j    = lane & 3;            // i-pair index 0..3
    const int o    = lane >> 2;           // output channel 0..7
    const int i0   = 2 * j;
    const int i1   = 2 * j + 1;

    // Per-channel coefficients (negate a for FMA form).
    const float b00 = b_coeff[(o * NI_I + i0) * 3 + 0];
    const float b01 = b_coeff[(o * NI_I + i0) * 3 + 1];
    const float b02 = b_coeff[(o * NI_I + i0) * 3 + 2];
    const float b10 = b_coeff[(o * NI_I + i1) * 3 + 0];
    const float b11 = b_coeff[(o * NI_I + i1) * 3 + 1];
    const float b12 = b_coeff[(o * NI_I + i1) * 3 + 2];
    const float na00 = -a_coeff[(o * NI_I + i0) * 2 + 0];
    const float na01 = -a_coeff[(o * NI_I + i0) * 2 + 1];
    const float na10 = -a_coeff[(o * NI_I + i1) * 2 + 0];
    const float na11 = -a_coeff[(o * NI_I + i1) * 2 + 1];

    const float* ub = u_in + (size_t)b * NT_T * NI_I;
    float*       yb = y_out + (size_t)b * NT_T * NO_O;

    const int t0 = c * CHUNK_L;

    float x1a, x2a, x1b, x2b;   // x[t-1], x[t-2] for the two chains
    float u1a, u2a, u1b, u2b;   // u[t-1], u[t-2]

    if (c == 0) {
        // Exact initial conditions from y_0 / u_0.
        x1a = y_0[((b * NO_O + o) * NI_I + i0) * 2 + 0];
        x2a = y_0[((b * NO_O + o) * NI_I + i0) * 2 + 1];
        x1b = y_0[((b * NO_O + o) * NI_I + i1) * 2 + 0];
        x2b = y_0[((b * NO_O + o) * NI_I + i1) * 2 + 1];
        u1a = u_0[(b * NI_I + i0) * 3 + 0];
        u2a = u_0[(b * NI_I + i0) * 3 + 1];
        u1b = u_0[(b * NI_I + i1) * 3 + 0];
        u2b = u_0[(b * NI_I + i1) * 3 + 1];
    } else {
        // Zero state; warm up over WARMUP steps reading real u.
        x1a = x2a = x1b = x2b = 0.0f;
        const int ts = t0 - WARMUP;     // >= 448, so ts-2 >= 0
        u1a = ub[(ts - 1) * NI_I + i0];
        u1b = ub[(ts - 1) * NI_I + i1];
        u2a = ub[(ts - 2) * NI_I + i0];
        u2b = ub[(ts - 2) * NI_I + i1];
        #pragma unroll 4
        for (int t = ts; t < t0; ++t) {
            const float2 u = *reinterpret_cast<const float2*>(ub + t * NI_I + i0);
            const float fa = fmaf(b02, u2a, fmaf(b01, u1a, b00 * u.x));
            const float fb = fmaf(b12, u2b, fmaf(b11, u1b, b10 * u.y));
            const float xa = fmaf(na00, x1a, fmaf(na01, x2a, fa));
            const float xb = fmaf(na10, x1b, fmaf(na11, x2b, fb));
            u2a = u1a; u1a = u.x;
            u2b = u1b; u1b = u.y;
            x2a = x1a; x1a = xa;
            x2b = x1b; x1b = xb;
        }
    }

    const bool writer = (j == 0);
    #pragma unroll 4
    for (int t = t0; t < t0 + CHUNK_L; ++t) {
        const float2 u = *reinterpret_cast<const float2*>(ub + t * NI_I + i0);
        const float fa = fmaf(b02, u2a, fmaf(b01, u1a, b00 * u.x));
        const float fb = fmaf(b12, u2b, fmaf(b11, u1b, b10 * u.y));
        const float xa = fmaf(na00, x1a, fmaf(na01, x2a, fa));
        const float xb = fmaf(na10, x1b, fmaf(na11, x2b, fb));
        u2a = u1a; u1a = u.x;
        u2b = u1b; u1b = u.y;
        x2a = x1a; x1a = xa;
        x2b = x1b; x1b = xb;

        float r = xa + xb;
        r += __shfl_xor_sync(0xffffffffu, r, 1);
        r += __shfl_xor_sync(0xffffffffu, r, 2);
        if (writer) yb[t * NO_O + o] = r;
    }
}

extern "C" void kernel_launch(void* const* d_in, const int* in_sizes, int n_in,
                              void* d_out, int out_size) {
    (void)in_sizes; (void)n_in; (void)out_size;
    const float* b_coeff = (const float*)d_in[0];
    const float* a_coeff = (const float*)d_in[1];
    const float* u_in    = (const float*)d_in[2];
    const float* y_0     = (const float*)d_in[3];
    const float* u_0     = (const float*)d_in[4];
    float* y_out = (float*)d_out;

    // 32768 threads = 1024 warps: (b, o, i-pair, chunk)
    linear_mimo_kernel<<<128, 256>>>(b_coeff, a_coeff, u_in, y_0, u_0, y_out);
}

// round 4
// speedup vs baseline: 1.4435x; 1.4435x over previous
#include <cuda_runtime.h>
#include <cstdint>

// LinearMimo: batched MIMO IIR filter. B=32, T=16384, I=O=8, NB=3, NA=2.
// Chunked-parallel (32 chunks of 512, 64-step warm-up; poles |l|<~0.5 so
// warm-up error ~2^-64). Warp = one (b, chunk); lane = (i-pair j, o).
// R3 fix: the old kernel was MLP=1 latency-bound (issue 12%, dram 2%).
//  - cp.async double(quad)-buffered smem tiles of u (1KB = 32 timesteps),
//    prefetch distance 2 -> global latency fully overlapped.
//  - packed fma.rn.f32x2: both chains of a lane in one instruction.

#define NB_B 32
#define NT_T 16384
#define NI_I 8
#define NO_O 8
#define NCHUNK 32
#define CHUNK_L 512
#define WARMUP 64
#define TILE_T 32           // timesteps per tile = 1KB
#define NBUF 4
#define DIST 2              // prefetch distance (tiles)

typedef unsigned long long u64;

__device__ __forceinline__ u64 pack2(float lo, float hi) {
    u64 r; asm("mov.b64 %0, {%1, %2};" : "=l"(r) : "f"(lo), "f"(hi)); return r;
}
__device__ __forceinline__ void unpack2(u64 v, float& lo, float& hi) {
    asm("mov.b64 {%0, %1}, %2;" : "=f"(lo), "=f"(hi) : "l"(v));
}
__device__ __forceinline__ u64 fma2(u64 a, u64 b, u64 c) {
    u64 d; asm("fma.rn.f32x2 %0, %1, %2, %3;" : "=l"(d) : "l"(a), "l"(b), "l"(c)); return d;
}
__device__ __forceinline__ u64 mul2(u64 a, u64 b) {
    u64 d; asm("mul.rn.f32x2 %0, %1, %2;" : "=l"(d) : "l"(a), "l"(b)); return d;
}
__device__ __forceinline__ void cp16(uint32_t saddr, const void* g) {
    asm volatile("cp.async.ca.shared.global [%0], [%1], 16;" :: "r"(saddr), "l"(g));
}
__device__ __forceinline__ void cp_commit() {
    asm volatile("cp.async.commit_group;" ::: "memory");
}
__device__ __forceinline__ void cp_wait(int n) {
    if (n >= 2)      asm volatile("cp.async.wait_group 2;" ::: "memory");
    else if (n == 1) asm volatile("cp.async.wait_group 1;" ::: "memory");
    else             asm volatile("cp.async.wait_group 0;" ::: "memory");
}

__global__ __launch_bounds__(256)
void linear_mimo_kernel(const float* __restrict__ b_coeff,   // (O, I, 3)
                        const float* __restrict__ a_coeff,   // (O, I, 2)
                        const float* __restrict__ u_in,      // (B, T, I)
                        const float* __restrict__ y_0,       // (B, O, I, 2)
                        const float* __restrict__ u_0,       // (B, I, 3)
                        float* __restrict__ y_out)           // (B, T, O)
{
    // 8 warps/block, 4 buffers/warp, 1KB each = 32KB
    __shared__ __align__(16) float smem_u[8 * NBUF * TILE_T * NI_I];

    const int lane = threadIdx.x & 31;
    const int wib  = threadIdx.x >> 5;
    const int w    = blockIdx.x * 8 + wib;   // 0..1023
    const int b    = w & (NB_B - 1);
    const int c    = w >> 5;                 // chunk 0..31
    const int j    = lane & 3;               // i-pair
    const int o    = lane >> 2;              // output channel
    const int i0   = 2 * j;
    const int i1   = 2 * j + 1;

    // Packed coefficients: lane {lo=chain i0, hi=chain i1}.
    const u64 B0 = pack2(b_coeff[(o * NI_I + i0) * 3 + 0], b_coeff[(o * NI_I + i1) * 3 + 0]);
    const u64 B1 = pack2(b_coeff[(o * NI_I + i0) * 3 + 1], b_coeff[(o * NI_I + i1) * 3 + 1]);
    const u64 B2 = pack2(b_coeff[(o * NI_I + i0) * 3 + 2], b_coeff[(o * NI_I + i1) * 3 + 2]);
    const u64 A0 = pack2(-a_coeff[(o * NI_I + i0) * 2 + 0], -a_coeff[(o * NI_I + i1) * 2 + 0]);
    const u64 A1 = pack2(-a_coeff[(o * NI_I + i0) * 2 + 1], -a_coeff[(o * NI_I + i1) * 2 + 1]);

    const float* ub = u_in + (size_t)b * NT_T * NI_I;
    float*       yb = y_out + (size_t)b * NT_T * NO_O;

    const int t0 = c * CHUNK_L;
    u64 X1, X2, U1, U2;

    int tstart, ntiles;
    if (c == 0) {
        tstart = t0; ntiles = CHUNK_L / TILE_T;                 // 16
        X1 = pack2(y_0[((b * NO_O + o) * NI_I + i0) * 2 + 0],
                   y_0[((b * NO_O + o) * NI_I + i1) * 2 + 0]);
        X2 = pack2(y_0[((b * NO_O + o) * NI_I + i0) * 2 + 1],
                   y_0[((b * NO_O + o) * NI_I + i1) * 2 + 1]);
        U1 = pack2(u_0[(b * NI_I + i0) * 3 + 0], u_0[(b * NI_I + i1) * 3 + 0]);
        U2 = pack2(u_0[(b * NI_I + i0) * 3 + 1], u_0[(b * NI_I + i1) * 3 + 1]);
    } else {
        tstart = t0 - WARMUP; ntiles = (CHUNK_L + WARMUP) / TILE_T;  // 18
        X1 = X2 = 0ull;
        U1 = *reinterpret_cast<const u64*>(ub + (tstart - 1) * NI_I + i0);
        U2 = *reinterpret_cast<const u64*>(ub + (tstart - 2) * NI_I + i0);
    }

    float* bufs = smem_u + wib * (NBUF * TILE_T * NI_I);

    // Prefetch one tile: 1KB contiguous, 32B per lane = 2x cp.async 16B.
    auto prefetch = [&](int tl) {
        float* dst = bufs + (tl & (NBUF - 1)) * (TILE_T * NI_I);
        uint32_t s = (uint32_t)__cvta_generic_to_shared(dst) + lane * 16;
        const char* g = (const char*)ub + ((size_t)(tstart + tl * TILE_T)) * (NI_I * 4) + lane * 16;
        cp16(s, g);
        cp16(s + 512, g + 512);
        cp_commit();
    };

    prefetch(0);
    if (ntiles > 1) prefetch(1);

    for (int tl = 0; tl < ntiles; ++tl) {
        if (tl + DIST < ntiles) prefetch(tl + DIST);
        int newer = min(ntiles - 1, tl + DIST) - tl;   // committed groups newer than tile tl
        cp_wait(newer);
        __syncwarp();

        const float* cur = bufs + (tl & (NBUF - 1)) * (TILE_T * NI_I);
        const int t_tile = tstart + tl * TILE_T;

        if (t_tile >= t0) {
            // output tile
            #pragma unroll 8
            for (int k = 0; k < TILE_T; ++k) {
                const u64 U = *reinterpret_cast<const u64*>(cur + k * NI_I + i0);
                const u64 F = fma2(B2, U2, fma2(B1, U1, mul2(B0, U)));
                const u64 X = fma2(A1, X2, fma2(A0, X1, F));
                U2 = U1; U1 = U; X2 = X1; X1 = X;
                float xl, xh; unpack2(X, xl, xh);
                float r = xl + xh;
                r += __shfl_xor_sync(0xffffffffu, r, 1);
                r += __shfl_xor_sync(0xffffffffu, r, 2);
                if (j == 0) yb[(t_tile + k) * NO_O + o] = r;
            }
        } else {
            // warm-up tile: no reduction/store
            #pragma unroll 8
            for (int k = 0; k < TILE_T; ++k) {
                const u64 U = *reinterpret_cast<const u64*>(cur + k * NI_I + i0);
                const u64 F = fma2(B2, U2, fma2(B1, U1, mul2(B0, U)));
                const u64 X = fma2(A1, X2, fma2(A0, X1, F));
                U2 = U1; U1 = U; X2 = X1; X1 = X;
            }
        }
        __syncwarp();
    }
}

extern "C" void kernel_launch(void* const* d_in, const int* in_sizes, int n_in,
                              void* d_out, int out_size) {
    (void)in_sizes; (void)n_in; (void)out_size;
    const float* b_coeff = (const float*)d_in[0];
    const float* a_coeff = (const float*)d_in[1];
    const float* u_in    = (const float*)d_in[2];
    const float* y_0     = (const float*)d_in[3];
    const float* u_0     = (const float*)d_in[4];
    float* y_out = (float*)d_out;

    linear_mimo_kernel<<<128, 256>>>(b_coeff, a_coeff, u_in, y_0, u_0, y_out);
}

// round 5
// speedup vs baseline: 3.5527x; 2.4611x over previous
#include <cuda_runtime.h>
#include <cstdint>

// LinearMimo: batched MIMO IIR. B=32, T=16384, I=O=8, NB=3, NA=2.
// R5: shuffle-free. One thread owns all 8 input chains (4 f32x2 pairs) for
// one (b, o, chunk); reduction over i is thread-local packed adds.
// Warp = (b, 4 chunks); lane = (q = chunk slot 0..3, o = 0..7).
// u tiles staged via cp.async (zero-fill for t<0); u row read by LDS.128
// with 8-way broadcast (conflict-free). 128 chunks of 128 steps + 64-step
// warm-up (poles |l|<~0.5 -> warm-up error ~2^-60, far under 1e-3).
// chunk 0 warms up on zero-filled input, then states are reset to the exact
// y_0/u_0 initial conditions before its output phase (warp stays convergent).

#define NB_B 32
#define NT_T 16384
#define NI_I 8
#define NO_O 8
#define CHUNK_L 128
#define NCHUNK  128
#define WARMUP  64
#define TILE_T  16
#define NBUF    4
#define DIST    2
#define WTILES  (WARMUP / TILE_T)              // 4
#define NTILES  ((CHUNK_L + WARMUP) / TILE_T)  // 12

typedef unsigned long long u64;

__device__ __forceinline__ u64 pack2(float lo, float hi) {
    u64 r; asm("mov.b64 %0, {%1, %2};" : "=l"(r) : "f"(lo), "f"(hi)); return r;
}
__device__ __forceinline__ void unpack2(u64 v, float& lo, float& hi) {
    asm("mov.b64 {%0, %1}, %2;" : "=f"(lo), "=f"(hi) : "l"(v));
}
__device__ __forceinline__ u64 fma2(u64 a, u64 b, u64 c) {
    u64 d; asm("fma.rn.f32x2 %0, %1, %2, %3;" : "=l"(d) : "l"(a), "l"(b), "l"(c)); return d;
}
__device__ __forceinline__ u64 mul2(u64 a, u64 b) {
    u64 d; asm("mul.rn.f32x2 %0, %1, %2;" : "=l"(d) : "l"(a), "l"(b)); return d;
}
__device__ __forceinline__ u64 add2(u64 a, u64 b) {
    u64 d; asm("add.rn.f32x2 %0, %1, %2;" : "=l"(d) : "l"(a), "l"(b)); return d;
}
__device__ __forceinline__ void cp16z(uint32_t saddr, const void* g, int sz) {
    asm volatile("cp.async.ca.shared.global [%0], [%1], 16, %2;"
                 :: "r"(saddr), "l"(g), "r"(sz));
}
__device__ __forceinline__ void cp_commit() {
    asm volatile("cp.async.commit_group;" ::: "memory");
}
__device__ __forceinline__ void cp_wait(int n) {
    if (n >= 2)      asm volatile("cp.async.wait_group 2;" ::: "memory");
    else if (n == 1) asm volatile("cp.async.wait_group 1;" ::: "memory");
    else             asm volatile("cp.async.wait_group 0;" ::: "memory");
}

__global__ __launch_bounds__(128)
void linear_mimo_kernel(const float* __restrict__ b_coeff,   // (O, I, 3)
                        const float* __restrict__ a_coeff,   // (O, I, 2)
                        const float* __restrict__ u_in,      // (B, T, I)
                        const float* __restrict__ y_0,       // (B, O, I, 2)
                        const float* __restrict__ u_0,       // (B, I, 3)
                        float* __restrict__ y_out)           // (B, T, O)
{
    // 4 warps/block * NBUF * 4 slices * TILE_T*8 floats = 32 KB
    __shared__ __align__(16) float smem_u[4 * NBUF * 4 * TILE_T * NI_I];

    const int lane = threadIdx.x & 31;
    const int wib  = threadIdx.x >> 5;
    const int w    = blockIdx.x * 4 + wib;   // 0..1023
    const int b    = w & (NB_B - 1);
    const int cg   = w >> 5;                 // chunk group 0..31
    const int o    = lane & 7;
    const int q    = lane >> 3;              // chunk slot 0..3
    const int chunk = cg * 4 + q;            // 0..127
    const int t0    = chunk * CHUNK_L;
    const int tstart = t0 - WARMUP;          // -64 for chunk 0

    // Packed coefficients per pair p: {lo = i=2p, hi = i=2p+1}
    u64 B0[4], B1[4], B2[4], A0[4], A1[4];
    #pragma unroll
    for (int p = 0; p < 4; ++p) {
        const int ia = o * NI_I + 2 * p, ib = ia + 1;
        B0[p] = pack2(b_coeff[ia * 3 + 0], b_coeff[ib * 3 + 0]);
        B1[p] = pack2(b_coeff[ia * 3 + 1], b_coeff[ib * 3 + 1]);
        B2[p] = pack2(b_coeff[ia * 3 + 2], b_coeff[ib * 3 + 2]);
        A0[p] = pack2(-a_coeff[ia * 2 + 0], -a_coeff[ib * 2 + 0]);
        A1[p] = pack2(-a_coeff[ia * 2 + 1], -a_coeff[ib * 2 + 1]);
    }

    const float* ub = u_in + (size_t)b * NT_T * NI_I;
    float*       yb = y_out + (size_t)b * NT_T * NO_O;

    u64 X1[4], X2[4], Up1[4], Up2[4];
    #pragma unroll
    for (int p = 0; p < 4; ++p) { X1[p] = X2[p] = Up1[p] = Up2[p] = 0ull; }

    float* wbuf = smem_u + wib * (NBUF * 4 * TILE_T * NI_I);
    const uint32_t wbuf_s = (uint32_t)__cvta_generic_to_shared(wbuf);

    // Prefetch tile tl: each lane fetches 64B of its own slice q
    // (rows [tstart_q + tl*16, +16), 512B per slice, split across 8 o-lanes).
    auto prefetch = [&](int tl) {
        const int bo = (tstart + tl * TILE_T) * 32 + o * 64;   // byte offset
        const uint32_t s = wbuf_s + (uint32_t)(((tl & (NBUF - 1)) * 4 + q) * 512 + o * 64);
        #pragma unroll
        for (int n = 0; n < 4; ++n) {
            const int off = bo + n * 16;
            const int sz  = (off >= 0) ? 16 : 0;
            const char* g = (const char*)ub + (off >= 0 ? off : 0);
            cp16z(s + n * 16, g, sz);
        }
        cp_commit();
    };

    prefetch(0);
    prefetch(1);

    #pragma unroll 1
    for (int tl = 0; tl < NTILES; ++tl) {
        if (tl + DIST < NTILES) prefetch(tl + DIST);
        cp_wait(min(NTILES - 1, tl + DIST) - tl);
        __syncwarp();

        const float* cur = wbuf + ((tl & (NBUF - 1)) * 4 + q) * (TILE_T * NI_I);
        const bool out_phase = (tl >= WTILES);
        const int t_tile = tstart + tl * TILE_T;

        if (out_phase) {
            #pragma unroll
            for (int k = 0; k < TILE_T; ++k) {
                const u64* row = (const u64*)(cur + k * NI_I);  // 2x LDS.128, 8-way bcast
                u64 S = 0ull;
                #pragma unroll
                for (int p = 0; p < 4; ++p) {
                    const u64 U = row[p];
                    const u64 F = fma2(B2[p], Up2[p], fma2(B1[p], Up1[p], mul2(B0[p], U)));
                    const u64 X = fma2(A1[p], X2[p], fma2(A0[p], X1[p], F));
                    Up2[p] = Up1[p]; Up1[p] = U;
                    X2[p] = X1[p];   X1[p] = X;
                    S = (p == 0) ? X : add2(S, X);
                }
                float sl, sh; unpack2(S, sl, sh);
                yb[(size_t)(t_tile + k) * NO_O + o] = sl + sh;
            }
        } else {
            #pragma unroll
            for (int k = 0; k < TILE_T; ++k) {
                const u64* row = (const u64*)(cur + k * NI_I);
                #pragma unroll
                for (int p = 0; p < 4; ++p) {
                    const u64 U = row[p];
                    const u64 F = fma2(B2[p], Up2[p], fma2(B1[p], Up1[p], mul2(B0[p], U)));
                    const u64 X = fma2(A1[p], X2[p], fma2(A0[p], X1[p], F));
                    Up2[p] = Up1[p]; Up1[p] = U;
                    X2[p] = X1[p];   X1[p] = X;
                }
            }
            // End of warm-up: chunk 0 gets exact initial conditions.
            if (tl == WTILES - 1 && chunk == 0) {
                #pragma unroll
                for (int p = 0; p < 4; ++p) {
                    const int ia = (b * NO_O + o) * NI_I + 2 * p;
                    X1[p] = pack2(y_0[ia * 2 + 0], y_0[(ia + 1) * 2 + 0]);
                    X2[p] = pack2(y_0[ia * 2 + 1], y_0[(ia + 1) * 2 + 1]);
                    const int iu = b * NI_I + 2 * p;
                    Up1[p] = pack2(u_0[iu * 3 + 0], u_0[(iu + 1) * 3 + 0]);
                    Up2[p] = pack2(u_0[iu * 3 + 1], u_0[(iu + 1) * 3 + 1]);
                }
            }
        }
        __syncwarp();
    }
}

extern "C" void kernel_launch(void* const* d_in, const int* in_sizes, int n_in,
                              void* d_out, int out_size) {
    (void)in_sizes; (void)n_in; (void)out_size;
    const float* b_coeff = (const float*)d_in[0];
    const float* a_coeff = (const float*)d_in[1];
    const float* u_in    = (const float*)d_in[2];
    const float* y_0     = (const float*)d_in[3];
    const float* u_0     = (const float*)d_in[4];
    float* y_out = (float*)d_out;

    // 1024 warps = 32 b * 32 chunk-groups; 4 warps/block -> 256 blocks.
    linear_mimo_kernel<<<256, 128>>>(b_coeff, a_coeff, u_in, y_0, u_0, y_out);
}